// round 6
// baseline (speedup 1.0000x reference)
#include <cuda_runtime.h>
#include <cuda_bf16.h>
#include <cstdint>
#include <math.h>

#define EPS 1e-5f

constexpr int BATCH = 32;
constexpr int S = 1024;
constexpr int D = 1024;

constexpr int PAD = 40;                       // bf16 per smem row (80B stride)
constexpr int ARR_BYTES = 128 * PAD * 2;      // 10240 B per operand array
constexpr int BUF_BYTES = 4 * ARR_BYTES;      // 40960 B (Ahi,Alo,Bhi,Blo)
constexpr int SMEM_DYN  = 2 * BUF_BYTES;      // 81920 B double buffered

// Scratch (allocation-free requirement -> __device__ globals)
__device__ float g_xtran[(size_t)BATCH * S * D];     // 128 MB
__device__ float g_weights[(size_t)BATCH * S * S];   // 128 MB
__device__ float g_xT[(size_t)BATCH * S * D];        // 128 MB
__device__ float g_rowsum[BATCH * S];

// ---------------------------------------------------------------------------
// helpers
// ---------------------------------------------------------------------------
__device__ __forceinline__ uint32_t smem_u32(const void* p) {
    uint32_t a;
    asm("{ .reg .u64 t; cvta.to.shared.u64 t, %1; cvt.u32.u64 %0, t; }" : "=r"(a) : "l"(p));
    return a;
}

__device__ __forceinline__ void ldsm4(uint32_t& r0, uint32_t& r1, uint32_t& r2, uint32_t& r3,
                                      uint32_t addr) {
    asm volatile("ldmatrix.sync.aligned.m8n8.x4.shared.b16 {%0,%1,%2,%3}, [%4];"
                 : "=r"(r0), "=r"(r1), "=r"(r2), "=r"(r3) : "r"(addr));
}

__device__ __forceinline__ void mma_bf16(float* c, const uint32_t* a, const uint32_t* b) {
    asm volatile(
        "mma.sync.aligned.m16n8k16.row.col.f32.bf16.bf16.f32 "
        "{%0,%1,%2,%3}, {%4,%5,%6,%7}, {%8,%9}, {%0,%1,%2,%3};"
        : "+f"(c[0]), "+f"(c[1]), "+f"(c[2]), "+f"(c[3])
        : "r"(a[0]), "r"(a[1]), "r"(a[2]), "r"(a[3]), "r"(b[0]), "r"(b[1]));
}

__device__ __forceinline__ void ld8(const float* __restrict__ p, float* d) {
    float4 v0 = *(const float4*)p;
    float4 v1 = *(const float4*)(p + 4);
    d[0] = v0.x; d[1] = v0.y; d[2] = v0.z; d[3] = v0.w;
    d[4] = v1.x; d[5] = v1.y; d[6] = v1.z; d[7] = v1.w;
}

__device__ __forceinline__ void split8(const float* f, __nv_bfloat16* hi, __nv_bfloat16* lo) {
    uint32_t hw[4], lw[4];
#pragma unroll
    for (int i = 0; i < 4; i++) {
        __nv_bfloat16 h0 = __float2bfloat16_rn(f[2 * i]);
        __nv_bfloat16 h1 = __float2bfloat16_rn(f[2 * i + 1]);
        __nv_bfloat16 l0 = __float2bfloat16_rn(f[2 * i]     - __bfloat162float(h0));
        __nv_bfloat16 l1 = __float2bfloat16_rn(f[2 * i + 1] - __bfloat162float(h1));
        hw[i] = (uint32_t)__bfloat16_as_ushort(h0) | ((uint32_t)__bfloat16_as_ushort(h1) << 16);
        lw[i] = (uint32_t)__bfloat16_as_ushort(l0) | ((uint32_t)__bfloat16_as_ushort(l1) << 16);
    }
    *(uint4*)hi = make_uint4(hw[0], hw[1], hw[2], hw[3]);
    *(uint4*)lo = make_uint4(lw[0], lw[1], lw[2], lw[3]);
}

// ---------------------------------------------------------------------------
// MMA block: one K=32 smem panel -> 96 HMMA per warp (3-term bf16 split)
// Identical to the R3-validated version.
// ---------------------------------------------------------------------------
__device__ __forceinline__ void mma_block(uint32_t base, uint32_t aOff, uint32_t bOff,
                                          float acc[4][4][4]) {
    const uint32_t aHi = base;
    const uint32_t aLo = base + ARR_BYTES;
    const uint32_t bHi = base + 2 * ARR_BYTES;
    const uint32_t bLo = base + 3 * ARR_BYTES;
#pragma unroll
    for (int ks = 0; ks < 2; ks++) {
        const uint32_t koff = ks * 32;   // 16 bf16 = 32B
        uint32_t ah[4][4], al[4][4], bhf[4][2], blf[4][2];

#pragma unroll
        for (int mf = 0; mf < 4; mf++)
            ldsm4(ah[mf][0], ah[mf][1], ah[mf][2], ah[mf][3],
                  aHi + aOff + mf * (16 * PAD * 2) + koff);
#pragma unroll
        for (int p = 0; p < 2; p++) {
            uint32_t r0, r1, r2, r3;
            ldsm4(r0, r1, r2, r3, bHi + bOff + p * (16 * PAD * 2) + koff);
            bhf[2 * p][0] = r0; bhf[2 * p][1] = r2;
            bhf[2 * p + 1][0] = r1; bhf[2 * p + 1][1] = r3;
        }
#pragma unroll
        for (int mf = 0; mf < 4; mf++)
#pragma unroll
            for (int nf = 0; nf < 4; nf++)
                mma_bf16(acc[mf][nf], ah[mf], bhf[nf]);

#pragma unroll
        for (int p = 0; p < 2; p++) {
            uint32_t r0, r1, r2, r3;
            ldsm4(r0, r1, r2, r3, bLo + bOff + p * (16 * PAD * 2) + koff);
            blf[2 * p][0] = r0; blf[2 * p][1] = r2;
            blf[2 * p + 1][0] = r1; blf[2 * p + 1][1] = r3;
        }
#pragma unroll
        for (int mf = 0; mf < 4; mf++)
#pragma unroll
            for (int nf = 0; nf < 4; nf++)
                mma_bf16(acc[mf][nf], ah[mf], blf[nf]);

#pragma unroll
        for (int mf = 0; mf < 4; mf++)
            ldsm4(al[mf][0], al[mf][1], al[mf][2], al[mf][3],
                  aLo + aOff + mf * (16 * PAD * 2) + koff);
#pragma unroll
        for (int mf = 0; mf < 4; mf++)
#pragma unroll
            for (int nf = 0; nf < 4; nf++)
                mma_bf16(acc[mf][nf], al[mf], bhf[nf]);
    }
}

// ---------------------------------------------------------------------------
// Mainloop: acc += A[128,1024] * B[128,1024]^T (both fp32, K-major, ld=1024)
// In-loop bf16 hi/lo split (R3 data path), NOW double-buffered: one sync/iter,
// conversion of panel ko+1 overlaps tensor-pipe drain of MMA(ko).
// ---------------------------------------------------------------------------
__device__ __forceinline__ void mma_mainloop(const float* __restrict__ A,
                                             const float* __restrict__ B,
                                             float acc[4][4][4]) {
    extern __shared__ __align__(16) char smraw[];

    const int tid = threadIdx.x;
    const int lane = tid & 31;
    const int wid = tid >> 5;
    const int wm = wid & 1;        // 0..1  (64-row slabs)
    const int wn = wid >> 1;       // 0..3  (32-col slabs)

#pragma unroll
    for (int i = 0; i < 4; i++)
#pragma unroll
        for (int j = 0; j < 4; j++)
#pragma unroll
            for (int k = 0; k < 4; k++) acc[i][j][k] = 0.f;

    // staging assignment: thread covers rows rA and rA+64, cols [kk, kk+8)
    const int rA = tid >> 2;
    const int kk = (tid & 3) * 8;

    float pA[16], pB[16];
    ld8(A + (size_t)rA * 1024 + kk, pA);
    ld8(A + (size_t)(rA + 64) * 1024 + kk, pA + 8);
    ld8(B + (size_t)rA * 1024 + kk, pB);
    ld8(B + (size_t)(rA + 64) * 1024 + kk, pB + 8);

    const uint32_t sb0 = smem_u32(smraw);
    const uint32_t eoff0 = (uint32_t)((rA * PAD + kk) * 2);          // byte offset, row rA
    const uint32_t eoff1 = (uint32_t)(((rA + 64) * PAD + kk) * 2);   // byte offset, row rA+64

    const int row16 = lane & 15;
    const int c8 = (lane >> 4) * 8;
    const uint32_t aOff = (uint32_t)((wm * 64 + row16) * (PAD * 2) + c8 * 2);
    const uint32_t bOff = (uint32_t)((wn * 32 + row16) * (PAD * 2) + c8 * 2);

    for (int ko = 0; ko < 32; ko++) {
        char* buf = smraw + (ko & 1) * BUF_BYTES;
        // split + store panel ko into buf (Ahi | Alo | Bhi | Blo)
        split8(pA,     (__nv_bfloat16*)(buf + eoff0),
                       (__nv_bfloat16*)(buf + ARR_BYTES + eoff0));
        split8(pA + 8, (__nv_bfloat16*)(buf + eoff1),
                       (__nv_bfloat16*)(buf + ARR_BYTES + eoff1));
        split8(pB,     (__nv_bfloat16*)(buf + 2 * ARR_BYTES + eoff0),
                       (__nv_bfloat16*)(buf + 3 * ARR_BYTES + eoff0));
        split8(pB + 8, (__nv_bfloat16*)(buf + 2 * ARR_BYTES + eoff1),
                       (__nv_bfloat16*)(buf + 3 * ARR_BYTES + eoff1));
        __syncthreads();   // buf[ko&1] ready; also fences MMA(ko-1) before STS(ko+1)

        if (ko < 31) {
            const float* An = A + (ko + 1) * 32;
            const float* Bn = B + (ko + 1) * 32;
            ld8(An + (size_t)rA * 1024 + kk, pA);
            ld8(An + (size_t)(rA + 64) * 1024 + kk, pA + 8);
            ld8(Bn + (size_t)rA * 1024 + kk, pB);
            ld8(Bn + (size_t)(rA + 64) * 1024 + kk, pB + 8);
        }

        mma_block(sb0 + (ko & 1) * BUF_BYTES, aOff, bOff, acc);
        // no trailing sync: next iter writes the other buffer; the overwrite of
        // THIS buffer (iter ko+2) is fenced by the sync at iter ko+1.
    }
}

// ---------------------------------------------------------------------------
// GEMM1: xtran = x @ W^T + bias
// ---------------------------------------------------------------------------
__global__ __launch_bounds__(256)
void gemm1_kernel(const float* __restrict__ X, const float* __restrict__ W,
                  const float* __restrict__ bias) {
    const int m0 = blockIdx.y * 128;
    const int n0 = blockIdx.x * 128;

    float acc[4][4][4];
    mma_mainloop(X + (size_t)m0 * 1024, W + (size_t)n0 * 1024, acc);

    const int lane = threadIdx.x & 31, wid = threadIdx.x >> 5;
    const int wm = wid & 1, wn = wid >> 1;

#pragma unroll
    for (int mf = 0; mf < 4; mf++)
#pragma unroll
        for (int nf = 0; nf < 4; nf++) {
            int col = n0 + wn * 32 + nf * 8 + (lane & 3) * 2;
            float b0 = __ldg(&bias[col]), b1 = __ldg(&bias[col + 1]);
#pragma unroll
            for (int h = 0; h < 2; h++) {
                int row = m0 + wm * 64 + mf * 16 + (lane >> 2) + h * 8;
                float2 v = make_float2(acc[mf][nf][h * 2 + 0] + b0,
                                       acc[mf][nf][h * 2 + 1] + b1);
                *(float2*)&g_xtran[(size_t)row * 1024 + col] = v;
            }
        }
}

// ---------------------------------------------------------------------------
// GEMM2: weights[b] = xtran[b] @ x[b]^T with decay/opinion/exp(tanh)/mask epilogue
// ---------------------------------------------------------------------------
__global__ __launch_bounds__(256)
void gemm2_kernel(const float* __restrict__ X, const float* __restrict__ go,
                  const float* __restrict__ po, const float* __restrict__ gprob) {
    const int b  = blockIdx.z;
    const int m0 = blockIdx.y * 128;
    const int n0 = blockIdx.x * 128;

    float acc[4][4][4];
    mma_mainloop(g_xtran + (size_t)b * S * D + (size_t)m0 * 1024,
                 X       + (size_t)b * S * D + (size_t)n0 * 1024, acc);

    const int lane = threadIdx.x & 31, wid = threadIdx.x >> 5;
    const int wm = wid & 1, wn = wid >> 1;
    const float gp = __ldg(gprob);
    float* Cb = g_weights + (size_t)b * S * S;

#pragma unroll
    for (int mf = 0; mf < 4; mf++) {
#pragma unroll
        for (int h = 0; h < 2; h++) {
            int s = m0 + wm * 64 + mf * 16 + (lane >> 2) + h * 8;
            const float* goP = go + ((size_t)b * S + s) * 5;
            const float* poP = po + ((size_t)b * S + s) * 5;
            float ow = gp * (__ldg(&goP[1]) + __ldg(&goP[2])) +
                       (1.f - gp) * (__ldg(&poP[3]) + __ldg(&poP[4]));
#pragma unroll
            for (int nf = 0; nf < 4; nf++) {
                int t0 = n0 + wn * 32 + nf * 8 + (lane & 3) * 2;
                float2 v;
#pragma unroll
                for (int j = 0; j < 2; j++) {
                    int t = t0 + j;
                    float w = acc[mf][nf][h * 2 + j] * ow;
                    float loc = fabsf((float)(s - t));
                    w = __fdividef(w, loc + EPS);
                    float e2 = __expf(2.f * w);
                    float th = 1.f - __fdividef(2.f, e2 + 1.f);
                    float r = __expf(th);
                    if (s == t) r = 0.f;
                    ((float*)&v)[j] = r;
                }
                *(float2*)&Cb[(size_t)s * S + t0] = v;
            }
        }
    }
}

// ---------------------------------------------------------------------------
// GEMM3: out[b] = (weights[b] / rowsum) @ x[b]  (B = xT, K-major over t)
// ---------------------------------------------------------------------------
__global__ __launch_bounds__(256)
void gemm3_kernel(float* __restrict__ out) {
    const int b  = blockIdx.z;
    const int m0 = blockIdx.y * 128;
    const int n0 = blockIdx.x * 128;

    float acc[4][4][4];
    mma_mainloop(g_weights + (size_t)b * S * S + (size_t)m0 * 1024,
                 g_xT      + (size_t)b * S * D + (size_t)n0 * 1024, acc);

    const int lane = threadIdx.x & 31, wid = threadIdx.x >> 5;
    const int wm = wid & 1, wn = wid >> 1;
    float* Cb = out + (size_t)b * S * D;

#pragma unroll
    for (int mf = 0; mf < 4; mf++)
#pragma unroll
        for (int h = 0; h < 2; h++) {
            int s = m0 + wm * 64 + mf * 16 + (lane >> 2) + h * 8;
            float sc = 1.f / (g_rowsum[b * S + s] + EPS);
#pragma unroll
            for (int nf = 0; nf < 4; nf++) {
                int c0 = n0 + wn * 32 + nf * 8 + (lane & 3) * 2;
                float2 v = make_float2(acc[mf][nf][h * 2 + 0] * sc,
                                       acc[mf][nf][h * 2 + 1] * sc);
                *(float2*)&Cb[(size_t)s * 1024 + c0] = v;
            }
        }
}

// ---------------------------------------------------------------------------
// Transpose x per batch: g_xT[b][d][t] = x[b][t][d]
// ---------------------------------------------------------------------------
__global__ __launch_bounds__(256)
void transpose_kernel(const float* __restrict__ X) {
    __shared__ float tile[32][33];
    int b = blockIdx.z;
    int t0 = blockIdx.x * 32;
    int d0 = blockIdx.y * 32;
    const float* src = X + (size_t)b * S * D;
    float* dst = g_xT + (size_t)b * S * D;
    int tx = threadIdx.x & 31, ty = threadIdx.x >> 5;
#pragma unroll
    for (int i = 0; i < 32; i += 8)
        tile[ty + i][tx] = src[(size_t)(t0 + ty + i) * D + d0 + tx];
    __syncthreads();
#pragma unroll
    for (int i = 0; i < 32; i += 8)
        dst[(size_t)(d0 + ty + i) * S + t0 + tx] = tile[tx][ty + i];
}

// ---------------------------------------------------------------------------
// Rowsum over weights rows
// ---------------------------------------------------------------------------
__global__ __launch_bounds__(256)
void rowsum_kernel() {
    const int row = blockIdx.x;
    const float* p = g_weights + (size_t)row * S;
    const int tid = threadIdx.x;

    float4 v = *(const float4*)&p[tid * 4];
    float s = v.x + v.y + v.z + v.w;
#pragma unroll
    for (int off = 16; off > 0; off >>= 1)
        s += __shfl_down_sync(0xFFFFFFFFu, s, off);

    __shared__ float warpsum[8];
    if ((tid & 31) == 0) warpsum[tid >> 5] = s;
    __syncthreads();
    if (tid < 8) {
        float t = warpsum[tid];
#pragma unroll
        for (int off = 4; off > 0; off >>= 1)
            t += __shfl_down_sync(0xFFu, t, off);
        if (tid == 0) g_rowsum[row] = t;
    }
}

// ---------------------------------------------------------------------------
extern "C" void kernel_launch(void* const* d_in, const int* in_sizes, int n_in,
                              void* d_out, int out_size)
{
    const float* x     = (const float*)d_in[0];  // [32,1024,1024]
    const float* W     = (const float*)d_in[1];  // [1024,1024]
    const float* bias  = (const float*)d_in[2];  // [1024]
    const float* go    = (const float*)d_in[3];  // [32,1024,5]
    const float* po    = (const float*)d_in[4];  // [32,1024,5]
    const float* gprob = (const float*)d_in[5];  // scalar
    float* out = (float*)d_out;

    cudaFuncSetAttribute(gemm1_kernel, cudaFuncAttributeMaxDynamicSharedMemorySize, SMEM_DYN);
    cudaFuncSetAttribute(gemm2_kernel, cudaFuncAttributeMaxDynamicSharedMemorySize, SMEM_DYN);
    cudaFuncSetAttribute(gemm3_kernel, cudaFuncAttributeMaxDynamicSharedMemorySize, SMEM_DYN);

    transpose_kernel<<<dim3(32, 32, BATCH), 256>>>(x);
    gemm1_kernel<<<dim3(8, 256), 256, SMEM_DYN>>>(x, W, bias);
    gemm2_kernel<<<dim3(8, 8, BATCH), 256, SMEM_DYN>>>(x, go, po, gprob);
    rowsum_kernel<<<dim3(BATCH * S), 256>>>();
    gemm3_kernel<<<dim3(8, 8, BATCH), 256, SMEM_DYN>>>(out);
}

// round 7
// speedup vs baseline: 1.3006x; 1.3006x over previous
#include <cuda_runtime.h>
#include <cuda_bf16.h>
#include <cstdint>
#include <math.h>

#define EPS 1e-5f

constexpr int BATCH = 32;
constexpr int S = 1024;
constexpr int D = 1024;

// Scratch (allocation-free requirement -> __device__ globals)
__device__ float g_xtran[(size_t)BATCH * S * D];     // 128 MB
__device__ float g_weights[(size_t)BATCH * S * S];   // 128 MB
__device__ float g_xT[(size_t)BATCH * S * D];        // 128 MB
__device__ float g_rowsum[BATCH * S];

// ---------------------------------------------------------------------------
// helpers
// ---------------------------------------------------------------------------
__device__ __forceinline__ uint32_t smem_u32(const void* p) {
    uint32_t a;
    asm("{ .reg .u64 t; cvta.to.shared.u64 t, %1; cvt.u32.u64 %0, t; }" : "=r"(a) : "l"(p));
    return a;
}

__device__ __forceinline__ void ldsm4(uint32_t& r0, uint32_t& r1, uint32_t& r2, uint32_t& r3,
                                      uint32_t addr) {
    asm volatile("ldmatrix.sync.aligned.m8n8.x4.shared.b16 {%0,%1,%2,%3}, [%4];"
                 : "=r"(r0), "=r"(r1), "=r"(r2), "=r"(r3) : "r"(addr));
}

__device__ __forceinline__ void mma_bf16(float* c, const uint32_t* a, const uint32_t* b) {
    asm volatile(
        "mma.sync.aligned.m16n8k16.row.col.f32.bf16.bf16.f32 "
        "{%0,%1,%2,%3}, {%4,%5,%6,%7}, {%8,%9}, {%0,%1,%2,%3};"
        : "+f"(c[0]), "+f"(c[1]), "+f"(c[2]), "+f"(c[3])
        : "r"(a[0]), "r"(a[1]), "r"(a[2]), "r"(a[3]), "r"(b[0]), "r"(b[1]));
}

__device__ __forceinline__ void ld8(const float* __restrict__ p, float* d) {
    float4 v0 = *(const float4*)p;
    float4 v1 = *(const float4*)(p + 4);
    d[0] = v0.x; d[1] = v0.y; d[2] = v0.z; d[3] = v0.w;
    d[4] = v1.x; d[5] = v1.y; d[6] = v1.z; d[7] = v1.w;
}

// fp32[8] -> bf16 hi[8], lo[8].  hi = rn(x); lo = rn(x - hi).
// Cheap path: pack hi via cvt.rn.bf16x2.f32, unpack exactly via shift/mask
// (bf16 -> f32 is <<16), residual, pack lo. 6 ops/pair vs ~10 before.
// Values are bit-identical to the previous implementation.
__device__ __forceinline__ void split8(const float* f, __nv_bfloat16* hi, __nv_bfloat16* lo) {
    uint32_t hw[4], lw[4];
#pragma unroll
    for (int i = 0; i < 4; i++) {
        float a = f[2 * i], b = f[2 * i + 1];
        uint32_t h;
        // first PTX source -> high half: hi16 = bf16(b), lo16 = bf16(a)
        asm("cvt.rn.bf16x2.f32 %0, %1, %2;" : "=r"(h) : "f"(b), "f"(a));
        float ha = __uint_as_float(h << 16);          // exact f32 of bf16(a)
        float hb = __uint_as_float(h & 0xFFFF0000u);  // exact f32 of bf16(b)
        uint32_t l;
        asm("cvt.rn.bf16x2.f32 %0, %1, %2;" : "=r"(l) : "f"(b - hb), "f"(a - ha));
        hw[i] = h; lw[i] = l;
    }
    *(uint4*)hi = make_uint4(hw[0], hw[1], hw[2], hw[3]);
    *(uint4*)lo = make_uint4(lw[0], lw[1], lw[2], lw[3]);
}

constexpr int PAD = 40;   // bf16 per smem row (80B stride: conflict-free ldmatrix)

// ---------------------------------------------------------------------------
// Mainloop: acc[4][4][4] += A[128,1024] * B[128,1024]^T (both K-major, ld=1024)
// via 3-term bf16-split mma.sync. CTA: 256 threads, warp grid 2(m) x 4(n),
// warp tile 64x32, K staged 32 per iteration, register prefetch.
// (R3-proven structure; only split8 internals changed.)
// ---------------------------------------------------------------------------
__device__ __forceinline__ void mma_mainloop(const float* __restrict__ A,
                                             const float* __restrict__ B,
                                             float acc[4][4][4]) {
    __shared__ __align__(16) __nv_bfloat16 sAhi[128 * PAD];
    __shared__ __align__(16) __nv_bfloat16 sAlo[128 * PAD];
    __shared__ __align__(16) __nv_bfloat16 sBhi[128 * PAD];
    __shared__ __align__(16) __nv_bfloat16 sBlo[128 * PAD];

    const int tid = threadIdx.x;
    const int lane = tid & 31;
    const int wid = tid >> 5;
    const int wm = wid & 1;        // 0..1  (64-row slabs)
    const int wn = wid >> 1;       // 0..3  (32-col slabs)

#pragma unroll
    for (int i = 0; i < 4; i++)
#pragma unroll
        for (int j = 0; j < 4; j++)
#pragma unroll
            for (int k = 0; k < 4; k++) acc[i][j][k] = 0.f;

    // staging assignment: thread covers rows rA and rA+64, cols [kk, kk+8)
    const int rA = tid >> 2;
    const int kk = (tid & 3) * 8;

    float pA[16], pB[16];
    ld8(A + (size_t)rA * 1024 + kk, pA);
    ld8(A + (size_t)(rA + 64) * 1024 + kk, pA + 8);
    ld8(B + (size_t)rA * 1024 + kk, pB);
    ld8(B + (size_t)(rA + 64) * 1024 + kk, pB + 8);

    const uint32_t aHi = smem_u32(sAhi), aLo = smem_u32(sAlo);
    const uint32_t bHi = smem_u32(sBhi), bLo = smem_u32(sBlo);
    const int row16 = lane & 15;
    const int c8 = (lane >> 4) * 8;
    const uint32_t aOff = (uint32_t)((wm * 64 + row16) * (PAD * 2)) + (uint32_t)(c8 * 2);
    const uint32_t bOff = (uint32_t)((wn * 32 + row16) * (PAD * 2)) + (uint32_t)(c8 * 2);

    for (int ko = 0; ko < 32; ko++) {
        split8(pA,     &sAhi[rA * PAD + kk],        &sAlo[rA * PAD + kk]);
        split8(pA + 8, &sAhi[(rA + 64) * PAD + kk], &sAlo[(rA + 64) * PAD + kk]);
        split8(pB,     &sBhi[rA * PAD + kk],        &sBlo[rA * PAD + kk]);
        split8(pB + 8, &sBhi[(rA + 64) * PAD + kk], &sBlo[(rA + 64) * PAD + kk]);
        __syncthreads();

        if (ko < 31) {
            const float* An = A + (ko + 1) * 32;
            const float* Bn = B + (ko + 1) * 32;
            ld8(An + (size_t)rA * 1024 + kk, pA);
            ld8(An + (size_t)(rA + 64) * 1024 + kk, pA + 8);
            ld8(Bn + (size_t)rA * 1024 + kk, pB);
            ld8(Bn + (size_t)(rA + 64) * 1024 + kk, pB + 8);
        }

#pragma unroll
        for (int ks = 0; ks < 2; ks++) {
            const uint32_t koff = ks * 32;   // 16 bf16 = 32 bytes
            uint32_t ah[4][4], al[4][4], bhf[4][2], blf[4][2];

#pragma unroll
            for (int mf = 0; mf < 4; mf++)
                ldsm4(ah[mf][0], ah[mf][1], ah[mf][2], ah[mf][3],
                      aHi + aOff + mf * (16 * PAD * 2) + koff);
#pragma unroll
            for (int p = 0; p < 2; p++) {
                uint32_t r0, r1, r2, r3;
                ldsm4(r0, r1, r2, r3, bHi + bOff + p * (16 * PAD * 2) + koff);
                bhf[2 * p][0] = r0; bhf[2 * p][1] = r2;
                bhf[2 * p + 1][0] = r1; bhf[2 * p + 1][1] = r3;
            }
#pragma unroll
            for (int mf = 0; mf < 4; mf++)
#pragma unroll
                for (int nf = 0; nf < 4; nf++)
                    mma_bf16(acc[mf][nf], ah[mf], bhf[nf]);

#pragma unroll
            for (int p = 0; p < 2; p++) {
                uint32_t r0, r1, r2, r3;
                ldsm4(r0, r1, r2, r3, bLo + bOff + p * (16 * PAD * 2) + koff);
                blf[2 * p][0] = r0; blf[2 * p][1] = r2;
                blf[2 * p + 1][0] = r1; blf[2 * p + 1][1] = r3;
            }
#pragma unroll
            for (int mf = 0; mf < 4; mf++)
#pragma unroll
                for (int nf = 0; nf < 4; nf++)
                    mma_bf16(acc[mf][nf], ah[mf], blf[nf]);

#pragma unroll
            for (int mf = 0; mf < 4; mf++)
                ldsm4(al[mf][0], al[mf][1], al[mf][2], al[mf][3],
                      aLo + aOff + mf * (16 * PAD * 2) + koff);
#pragma unroll
            for (int mf = 0; mf < 4; mf++)
#pragma unroll
                for (int nf = 0; nf < 4; nf++)
                    mma_bf16(acc[mf][nf], al[mf], bhf[nf]);
        }
        __syncthreads();
    }
}

// ---------------------------------------------------------------------------
// Dummy first launch: zeroes g_rowsum (rewritten by rowsum_kernel later).
// Exists so the ncu capture (4th launch) lands on gemm2_kernel.
// ---------------------------------------------------------------------------
__global__ __launch_bounds__(256)
void dummy_zero_kernel() {
    int i = blockIdx.x * 256 + threadIdx.x;
    if (i < BATCH * S) g_rowsum[i] = 0.f;
}

// ---------------------------------------------------------------------------
// GEMM1: xtran = x @ W^T + bias
// ---------------------------------------------------------------------------
__global__ __launch_bounds__(256)
void gemm1_kernel(const float* __restrict__ X, const float* __restrict__ W,
                  const float* __restrict__ bias) {
    const int m0 = blockIdx.y * 128;
    const int n0 = blockIdx.x * 128;

    float acc[4][4][4];
    mma_mainloop(X + (size_t)m0 * 1024, W + (size_t)n0 * 1024, acc);

    const int lane = threadIdx.x & 31, wid = threadIdx.x >> 5;
    const int wm = wid & 1, wn = wid >> 1;

#pragma unroll
    for (int mf = 0; mf < 4; mf++)
#pragma unroll
        for (int nf = 0; nf < 4; nf++) {
            int col = n0 + wn * 32 + nf * 8 + (lane & 3) * 2;
            float b0 = __ldg(&bias[col]), b1 = __ldg(&bias[col + 1]);
#pragma unroll
            for (int h = 0; h < 2; h++) {
                int row = m0 + wm * 64 + mf * 16 + (lane >> 2) + h * 8;
                float2 v = make_float2(acc[mf][nf][h * 2 + 0] + b0,
                                       acc[mf][nf][h * 2 + 1] + b1);
                *(float2*)&g_xtran[(size_t)row * 1024 + col] = v;
            }
        }
}

// ---------------------------------------------------------------------------
// GEMM2: weights[b] = xtran[b] @ x[b]^T with decay/opinion/exp(tanh)/mask epilogue
// ---------------------------------------------------------------------------
__global__ __launch_bounds__(256)
void gemm2_kernel(const float* __restrict__ X, const float* __restrict__ go,
                  const float* __restrict__ po, const float* __restrict__ gprob) {
    const int b  = blockIdx.z;
    const int m0 = blockIdx.y * 128;
    const int n0 = blockIdx.x * 128;

    float acc[4][4][4];
    mma_mainloop(g_xtran + (size_t)b * S * D + (size_t)m0 * 1024,
                 X       + (size_t)b * S * D + (size_t)n0 * 1024, acc);

    const int lane = threadIdx.x & 31, wid = threadIdx.x >> 5;
    const int wm = wid & 1, wn = wid >> 1;
    const float gp = __ldg(gprob);
    float* Cb = g_weights + (size_t)b * S * S;

#pragma unroll
    for (int mf = 0; mf < 4; mf++) {
#pragma unroll
        for (int h = 0; h < 2; h++) {
            int s = m0 + wm * 64 + mf * 16 + (lane >> 2) + h * 8;
            const float* goP = go + ((size_t)b * S + s) * 5;
            const float* poP = po + ((size_t)b * S + s) * 5;
            float ow = gp * (__ldg(&goP[1]) + __ldg(&goP[2])) +
                       (1.f - gp) * (__ldg(&poP[3]) + __ldg(&poP[4]));
#pragma unroll
            for (int nf = 0; nf < 4; nf++) {
                int t0 = n0 + wn * 32 + nf * 8 + (lane & 3) * 2;
                float2 v;
#pragma unroll
                for (int j = 0; j < 2; j++) {
                    int t = t0 + j;
                    float w = acc[mf][nf][h * 2 + j] * ow;
                    float loc = fabsf((float)(s - t));
                    w = __fdividef(w, loc + EPS);
                    float e2 = __expf(2.f * w);
                    float th = 1.f - __fdividef(2.f, e2 + 1.f);
                    float r = __expf(th);
                    if (s == t) r = 0.f;
                    ((float*)&v)[j] = r;
                }
                *(float2*)&Cb[(size_t)s * S + t0] = v;
            }
        }
    }
}

// ---------------------------------------------------------------------------
// GEMM3: out[b] = (weights[b] / rowsum) @ x[b]  (B = xT, K-major over t)
// ---------------------------------------------------------------------------
__global__ __launch_bounds__(256)
void gemm3_kernel(float* __restrict__ out) {
    const int b  = blockIdx.z;
    const int m0 = blockIdx.y * 128;
    const int n0 = blockIdx.x * 128;

    float acc[4][4][4];
    mma_mainloop(g_weights + (size_t)b * S * S + (size_t)m0 * 1024,
                 g_xT      + (size_t)b * S * D + (size_t)n0 * 1024, acc);

    const int lane = threadIdx.x & 31, wid = threadIdx.x >> 5;
    const int wm = wid & 1, wn = wid >> 1;
    float* Cb = out + (size_t)b * S * D;

#pragma unroll
    for (int mf = 0; mf < 4; mf++)
#pragma unroll
        for (int h = 0; h < 2; h++) {
            int s = m0 + wm * 64 + mf * 16 + (lane >> 2) + h * 8;
            float sc = 1.f / (g_rowsum[b * S + s] + EPS);
#pragma unroll
            for (int nf = 0; nf < 4; nf++) {
                int c0 = n0 + wn * 32 + nf * 8 + (lane & 3) * 2;
                float2 v = make_float2(acc[mf][nf][h * 2 + 0] * sc,
                                       acc[mf][nf][h * 2 + 1] * sc);
                *(float2*)&Cb[(size_t)s * 1024 + c0] = v;
            }
        }
}

// ---------------------------------------------------------------------------
// Transpose x per batch: g_xT[b][d][t] = x[b][t][d]
// ---------------------------------------------------------------------------
__global__ __launch_bounds__(256)
void transpose_kernel(const float* __restrict__ X) {
    __shared__ float tile[32][33];
    int b = blockIdx.z;
    int t0 = blockIdx.x * 32;
    int d0 = blockIdx.y * 32;
    const float* src = X + (size_t)b * S * D;
    float* dst = g_xT + (size_t)b * S * D;
    int tx = threadIdx.x & 31, ty = threadIdx.x >> 5;
#pragma unroll
    for (int i = 0; i < 32; i += 8)
        tile[ty + i][tx] = src[(size_t)(t0 + ty + i) * D + d0 + tx];
    __syncthreads();
#pragma unroll
    for (int i = 0; i < 32; i += 8)
        dst[(size_t)(d0 + ty + i) * S + t0 + tx] = tile[tx][ty + i];
}

// ---------------------------------------------------------------------------
// Rowsum over weights rows
// ---------------------------------------------------------------------------
__global__ __launch_bounds__(256)
void rowsum_kernel() {
    const int row = blockIdx.x;
    const float* p = g_weights + (size_t)row * S;
    const int tid = threadIdx.x;

    float4 v = *(const float4*)&p[tid * 4];
    float s = v.x + v.y + v.z + v.w;
#pragma unroll
    for (int off = 16; off > 0; off >>= 1)
        s += __shfl_down_sync(0xFFFFFFFFu, s, off);

    __shared__ float warpsum[8];
    if ((tid & 31) == 0) warpsum[tid >> 5] = s;
    __syncthreads();
    if (tid < 8) {
        float t = warpsum[tid];
#pragma unroll
        for (int off = 4; off > 0; off >>= 1)
            t += __shfl_down_sync(0xFFu, t, off);
        if (tid == 0) g_rowsum[row] = t;
    }
}

// ---------------------------------------------------------------------------
extern "C" void kernel_launch(void* const* d_in, const int* in_sizes, int n_in,
                              void* d_out, int out_size)
{
    const float* x     = (const float*)d_in[0];  // [32,1024,1024]
    const float* W     = (const float*)d_in[1];  // [1024,1024]
    const float* bias  = (const float*)d_in[2];  // [1024]
    const float* go    = (const float*)d_in[3];  // [32,1024,5]
    const float* po    = (const float*)d_in[4];  // [32,1024,5]
    const float* gprob = (const float*)d_in[5];  // scalar
    float* out = (float*)d_out;

    // Launch order chosen so ncu's captured launch (#4) is gemm2_kernel.
    dummy_zero_kernel<<<BATCH * S / 256, 256>>>();                  // 1
    transpose_kernel<<<dim3(32, 32, BATCH), 256>>>(x);              // 2
    gemm1_kernel<<<dim3(8, 256), 256>>>(x, W, bias);                // 3
    gemm2_kernel<<<dim3(8, 8, BATCH), 256>>>(x, go, po, gprob);     // 4  <- profiled
    rowsum_kernel<<<dim3(BATCH * S), 256>>>();                      // 5
    gemm3_kernel<<<dim3(8, 8, BATCH), 256>>>(out);                  // 6
}